// round 4
// baseline (speedup 1.0000x reference)
#include <cuda_runtime.h>
#include <cuda_fp16.h>
#include <cstdint>

#define Hdim  1024
#define Bsz   64
#define Tlen  512
#define FOURH 4096
#define KTOT  2048
#define KEFF  4096            // [Whi(2048) | Wlo(2048)]
#define NTILE 128
#define KC    64
#define NCHUNK (KEFF / KC)    // 64

// ---------------- persistent scratch (device globals; no allocations) -------
__device__ __align__(16) __half g_W[4ull * FOURH * KEFF];        // 134MB: [cell][n'][khi|klo]
__device__ __align__(16) float  g_bias[4 * FOURH];
__device__ __align__(16) __half g_xh[(size_t)Bsz * Tlen * Hdim]; // 67MB
__device__ __align__(16) __half g_hf0[2][Bsz * Hdim];
__device__ __align__(16) __half g_hb0[2][Bsz * Hdim];
__device__ __align__(16) float  g_cb0[2][Bsz * Hdim];
__device__ __align__(16) __half g_hb1[2][Bsz * Hdim];
__device__ __align__(16) float  g_cb1[2][Bsz * Hdim];

// ---------------- prep kernels ---------------------------------------------
// Weight layout: cell 0=f0, 1=b0, 2=f1, 3=b1.
// Row reorder: n' = 4*h + gate  (source row n = gate*H + h).
// K layout: kk in [0,4096). khalf = kk&2047: khalf<H -> Wih (feature-reversed
// for cell 1), khalf>=H -> Whh. kk<2048 -> fp16 hi part, kk>=2048 -> lo residual.
__global__ void prep_weights(const float* __restrict__ Wih_f, const float* __restrict__ Whh_f,
                             const float* __restrict__ Wih_b, const float* __restrict__ Whh_b) {
    long idx = (long)blockIdx.x * 256 + threadIdx.x;
    if (idx >= 4L * FOURH * KEFF) return;
    int  cell = (int)(idx / ((long)FOURH * KEFF));
    long rem  = idx % ((long)FOURH * KEFF);
    int  np   = (int)(rem / KEFF);
    int  kk   = (int)(rem % KEFF);
    int  part = kk >> 11;           // 0 = hi, 1 = lo
    int  kh   = kk & (KTOT - 1);
    int  h = np >> 2, g = np & 3;
    int  n = g * Hdim + h;
    int  layer = cell >> 1;
    bool bwd   = cell & 1;
    float v;
    if (kh < Hdim) {
        int ksrc = (bwd && layer == 0) ? (Hdim - 1 - kh) : kh;  // feature reversal baked in
        const float* Wih = bwd ? Wih_b : Wih_f;
        v = Wih[((long)layer * FOURH + n) * Hdim + ksrc];
    } else {
        const float* Whh = bwd ? Whh_b : Whh_f;
        v = Whh[((long)layer * FOURH + n) * Hdim + (kh - Hdim)];
    }
    __half hi = __float2half_rn(v);
    if (part == 0) g_W[idx] = hi;
    else           g_W[idx] = __float2half_rn(v - __half2float(hi));
}

__global__ void prep_x(const float* __restrict__ x) {
    long idx = (long)blockIdx.x * 256 + threadIdx.x;
    if (idx >= (long)Bsz * Tlen * Hdim) return;
    g_xh[idx] = __float2half_rn(x[idx]);
}

__global__ void prep_bias(const float* __restrict__ bih_f, const float* __restrict__ bhh_f,
                          const float* __restrict__ bih_b, const float* __restrict__ bhh_b) {
    int idx = blockIdx.x * 256 + threadIdx.x;
    if (idx >= 4 * FOURH) return;
    int cell = idx / FOURH, np = idx % FOURH;
    int h = np >> 2, g = np & 3;
    int n = g * Hdim + h;
    int layer = cell >> 1;
    bool bwd = cell & 1;
    const float* bi = bwd ? bih_b : bih_f;
    const float* bh = bwd ? bhh_b : bhh_f;
    g_bias[idx] = bi[layer * FOURH + n] + bh[layer * FOURH + n];
}

__global__ void prep_zero() {
    int idx = blockIdx.x * 256 + threadIdx.x;
    if (idx >= Bsz * Hdim) return;
    __half z = __float2half_rn(0.f);
    g_hf0[0][idx] = z; g_hf0[1][idx] = z;
    g_hb0[0][idx] = z; g_hb0[1][idx] = z;
    g_hb1[0][idx] = z; g_hb1[1][idx] = z;
    g_cb0[0][idx] = 0.f; g_cb0[1][idx] = 0.f;
    g_cb1[0][idx] = 0.f; g_cb1[1][idx] = 0.f;
}

// ---------------- step kernel ----------------------------------------------
// Launch k (0..512): cells 0,1 do layer-0 at t=k (k<512); cells 2,3 do
// layer-1 at t=k-1 (k>=1). One logical GEMM per cell: [64 x 4096] where the
// A operand wraps ([x|h|x|h]) and W = [Whi | Wlo] -> A*Whi + A*Wlo exactly
// compensates the fp16 weight quantization. fp32 accumulate.
#define AS_ELEMS (64 * 72)
#define BS_ELEMS (128 * 72)
#define SMEM_B_OFF  18432
#define SMEM_G_OFF  55296
#define SMEM_TOTAL  88064

__device__ __forceinline__ void cp16(uint32_t dst, const void* src) {
    asm volatile("cp.async.cg.shared.global [%0], [%1], 16;\n" :: "r"(dst), "l"(src));
}

__global__ __launch_bounds__(256) void step_kernel(int k, float* __restrict__ out) {
    const int cell = blockIdx.y;
    if (cell < 2) { if (k >= Tlen) return; } else { if (k == 0) return; }
    const int jt = blockIdx.x;           // N-tile 0..31 -> hidden units [jt*32, jt*32+32)

    extern __shared__ char smem[];
    __half* As = (__half*)smem;
    __half* Bs = (__half*)(smem + SMEM_B_OFF);
    float* gates = (float*)(smem + SMEM_G_OFF);
    uint32_t smem_u32 = (uint32_t)__cvta_generic_to_shared(smem);

    const int tid  = threadIdx.x;
    const int warp = tid >> 5;
    const int lane = tid & 31;
    const int gid  = lane >> 2, tig = lane & 3;
    const int wM   = warp >> 2, wN = warp & 3;   // 2 x 4 warp grid

    const int t  = (cell < 2) ? k : (k - 1);
    const int pp = t & 1, pm = pp ^ 1;

    // A operand sources: first K-half and second K-half (each 1024 wide)
    const __half *a0base, *a1base;
    long a0stride, a1stride;
    if (cell < 2) {
        a0base = g_xh + (long)t * Hdim;  a0stride = (long)Tlen * Hdim;  // x_t
        a1base = g_hb0[pm];              a1stride = Hdim;               // h_b0(t-1)
    } else if (cell == 2) {
        a0base = g_hf0[pp];              a0stride = Hdim;               // h_f0(t)
        a1base = g_hb1[pm];              a1stride = Hdim;               // h_b1(t-1)
    } else {
        a0base = g_hb0[pp];              a0stride = Hdim;               // h_b0(t)
        a1base = g_hb1[pm];              a1stride = Hdim;               // h_b1(t-1)
    }
    const __half* Wg = g_W + ((long)cell * FOURH + (long)jt * NTILE) * KEFF;

    float acc[2][4][4];
#pragma unroll
    for (int i = 0; i < 2; i++)
#pragma unroll
        for (int j = 0; j < 4; j++)
#pragma unroll
            for (int q = 0; q < 4; q++) acc[i][j][q] = 0.f;

    auto load_chunk = [&](int c, int buf) {
        int kg = c * KC;                  // 0..4032, position in W's K axis
        int kw = kg & (KTOT - 1);         // A operand wraps: [x|h|x|h]
        const __half* ab; long astr; int koff;
        if (kw < Hdim) { ab = a0base; astr = a0stride; koff = kw; }
        else           { ab = a1base; astr = a1stride; koff = kw - Hdim; }
#pragma unroll
        for (int it = 0; it < 2; it++) {                 // A: 64 rows x 8 16B-chunks
            int idx = tid + it * 256;
            int r = idx >> 3, c8 = idx & 7;
            const void* src = ab + (long)r * astr + koff + c8 * 8;
            uint32_t dst = smem_u32 + (uint32_t)(buf * AS_ELEMS + r * 72 + c8 * 8) * 2;
            cp16(dst, src);
        }
#pragma unroll
        for (int it = 0; it < 4; it++) {                 // B: 128 rows x 8 16B-chunks
            int idx = tid + it * 256;
            int r = idx >> 3, c8 = idx & 7;
            const void* src = Wg + (long)r * KEFF + kg + c8 * 8;
            uint32_t dst = smem_u32 + SMEM_B_OFF + (uint32_t)(buf * BS_ELEMS + r * 72 + c8 * 8) * 2;
            cp16(dst, src);
        }
        asm volatile("cp.async.commit_group;\n");
    };

    auto compute_chunk = [&](int buf) {
        const __half* Ab = As + buf * AS_ELEMS;
        const __half* Bb = Bs + buf * BS_ELEMS;
#pragma unroll
        for (int k16 = 0; k16 < 4; k16++) {
            int ko = k16 * 16;
            uint32_t a[2][4], b[4][2];
#pragma unroll
            for (int i = 0; i < 2; i++) {
                int r0 = wM * 32 + i * 16 + gid;
                a[i][0] = *(const uint32_t*)(Ab + r0 * 72 + ko + 2 * tig);
                a[i][1] = *(const uint32_t*)(Ab + (r0 + 8) * 72 + ko + 2 * tig);
                a[i][2] = *(const uint32_t*)(Ab + r0 * 72 + ko + 8 + 2 * tig);
                a[i][3] = *(const uint32_t*)(Ab + (r0 + 8) * 72 + ko + 8 + 2 * tig);
            }
#pragma unroll
            for (int j = 0; j < 4; j++) {
                int n0 = wN * 32 + j * 8 + gid;
                b[j][0] = *(const uint32_t*)(Bb + n0 * 72 + ko + 2 * tig);
                b[j][1] = *(const uint32_t*)(Bb + n0 * 72 + ko + 8 + 2 * tig);
            }
#pragma unroll
            for (int i = 0; i < 2; i++)
#pragma unroll
                for (int j = 0; j < 4; j++) {
                    asm volatile(
                        "mma.sync.aligned.m16n8k16.row.col.f32.f16.f16.f32 "
                        "{%0,%1,%2,%3}, {%4,%5,%6,%7}, {%8,%9}, {%0,%1,%2,%3};\n"
                        : "+f"(acc[i][j][0]), "+f"(acc[i][j][1]),
                          "+f"(acc[i][j][2]), "+f"(acc[i][j][3])
                        : "r"(a[i][0]), "r"(a[i][1]), "r"(a[i][2]), "r"(a[i][3]),
                          "r"(b[j][0]), "r"(b[j][1]));
                }
        }
    };

    // double-buffered mainloop
    load_chunk(0, 0);
    for (int c = 0; c < NCHUNK; c++) {
        int cur = c & 1;
        if (c + 1 < NCHUNK) {
            load_chunk(c + 1, cur ^ 1);
            asm volatile("cp.async.wait_group 1;\n");
        } else {
            asm volatile("cp.async.wait_group 0;\n");
        }
        __syncthreads();
        compute_chunk(cur);
        __syncthreads();
    }

    // epilogue: accum frags -> smem gates [64][128]
#pragma unroll
    for (int i = 0; i < 2; i++)
#pragma unroll
        for (int j = 0; j < 4; j++) {
            int r0 = wM * 32 + i * 16 + gid;
            int cb = wN * 32 + j * 8 + 2 * tig;
            gates[r0 * 128 + cb]           = acc[i][j][0];
            gates[r0 * 128 + cb + 1]       = acc[i][j][1];
            gates[(r0 + 8) * 128 + cb]     = acc[i][j][2];
            gates[(r0 + 8) * 128 + cb + 1] = acc[i][j][3];
        }
    __syncthreads();

    const float* bias  = g_bias + cell * FOURH + jt * NTILE;
    const float* cprev = (cell < 2) ? g_cb0[pm] : g_cb1[pm];

    for (int p = tid; p < 2048; p += 256) {
        int b  = p >> 5, hl = p & 31;
        int hg = jt * 32 + hl;
        float ig = gates[b * 128 + 4 * hl + 0] + bias[4 * hl + 0];
        float fg = gates[b * 128 + 4 * hl + 1] + bias[4 * hl + 1];
        float gg = gates[b * 128 + 4 * hl + 2] + bias[4 * hl + 2];
        float og = gates[b * 128 + 4 * hl + 3] + bias[4 * hl + 3];
        float cp = cprev[b * Hdim + hg];
        float si = 1.f / (1.f + __expf(-ig));
        float sf = 1.f / (1.f + __expf(-fg));
        float so = 1.f / (1.f + __expf(-og));
        float cn = sf * cp + si * tanhf(gg);
        float hn = so * tanhf(cn);
        long sidx = (long)b * Hdim + hg;
        if (cell == 0) {                                  // f0: h feeds layer1, c discarded
            g_hf0[pp][sidx] = __float2half_rn(hn);
        } else if (cell == 1) {                           // b0: the layer-0 carry
            g_hb0[pp][sidx] = __float2half_rn(hn);
            g_cb0[pp][sidx] = cn;
        } else {                                          // layer 1 -> outputs
            int halfoff = (cell == 2) ? 0 : Hdim;
            long oidx = ((long)b * Tlen + t) * (2 * Hdim) + halfoff + hg;
            out[oidx] = hn;
            out[(long)Bsz * Tlen * 2 * Hdim + oidx] = cn;
            if (t == Tlen - 1) {
                long lbase = 2L * Bsz * Tlen * 2 * Hdim;
                out[lbase + (long)b * 2 * Hdim + halfoff + hg] = hn;
                out[lbase + (long)Bsz * 2 * Hdim + (long)b * 2 * Hdim + halfoff + hg] = cn;
            }
            if (cell == 3) {                              // b1: the layer-1 carry
                g_hb1[pp][sidx] = __float2half_rn(hn);
                g_cb1[pp][sidx] = cn;
            }
        }
    }
}

// ---------------- launcher --------------------------------------------------
extern "C" void kernel_launch(void* const* d_in, const int* in_sizes, int n_in,
                              void* d_out, int out_size) {
    const float* x     = (const float*)d_in[0];
    const float* Wih_f = (const float*)d_in[1];
    const float* Whh_f = (const float*)d_in[2];
    const float* bih_f = (const float*)d_in[3];
    const float* bhh_f = (const float*)d_in[4];
    const float* Wih_b = (const float*)d_in[5];
    const float* Whh_b = (const float*)d_in[6];
    const float* bih_b = (const float*)d_in[7];
    const float* bhh_b = (const float*)d_in[8];
    float* out = (float*)d_out;

    cudaFuncSetAttribute(step_kernel, cudaFuncAttributeMaxDynamicSharedMemorySize, SMEM_TOTAL);

    {
        long n = 4L * FOURH * KEFF;
        prep_weights<<<(unsigned)((n + 255) / 256), 256>>>(Wih_f, Whh_f, Wih_b, Whh_b);
    }
    {
        long n = (long)Bsz * Tlen * Hdim;
        prep_x<<<(unsigned)((n + 255) / 256), 256>>>(x);
    }
    prep_bias<<<(4 * FOURH + 255) / 256, 256>>>(bih_f, bhh_f, bih_b, bhh_b);
    prep_zero<<<(Bsz * Hdim + 255) / 256, 256>>>();

    for (int k = 0; k <= Tlen; k++) {
        step_kernel<<<dim3(32, 4), 256, SMEM_TOTAL>>>(k, out);
    }
}